// round 7
// baseline (speedup 1.0000x reference)
#include <cuda_runtime.h>
#include <math.h>
#include <stdint.h>

// Problem constants
constexpr int C_B    = 2;
constexpr int C_T    = 2048;
constexpr int C_HID  = 2048;
constexpr int C_H    = 16;
constexpr int C_D    = 128;
constexpr int C_WIN  = 512;
constexpr int C_QC   = 512;
constexpr int C_G    = 4;
constexpr int C_INTER= 2048;
constexpr int C_TOK  = C_B * C_T;

// ---------------------------------------------------------------------------
// Scratch (device globals)
// ---------------------------------------------------------------------------
__device__ float g_h_hi [C_TOK * C_HID];
__device__ float g_h_lo [C_TOK * C_HID];
__device__ float g_hc_hi[C_TOK * C_QC];
__device__ float g_hc_lo[C_TOK * C_QC];
__device__ float g_q    [C_TOK * C_H * C_D];
__device__ float g_kv   [C_TOK * 2 * C_D];
__device__ float g_att  [C_TOK * C_H * C_D];
__device__ float g_y1   [C_TOK * C_G * C_INTER];
// Transposed (+rounded) weights: [N][K]
__device__ float g_wqcT_hi[C_QC * C_HID];
__device__ float g_wqcT_lo[C_QC * C_HID];
__device__ float g_wquT_hi[C_H * C_D * C_QC];
__device__ float g_wquT_lo[C_H * C_D * C_QC];
__device__ float g_wkvT_hi[2 * C_D * C_HID];
__device__ float g_wkvT_lo[2 * C_D * C_HID];
__device__ float g_w1T [C_G * C_INTER * (C_H / C_G) * C_D];
__device__ float g_w2T [C_HID * C_G * C_INTER];

__device__ __forceinline__ uint32_t f2tf32(float f) {
    uint32_t r;
    asm("cvt.rna.tf32.f32 %0, %1;" : "=r"(r) : "f"(f));
    return r;
}
__device__ __forceinline__ float tf32r(float f) { return __uint_as_float(f2tf32(f)); }

__device__ __forceinline__ void mma_tf32(float& c0, float& c1, float& c2, float& c3,
                                         uint32_t a0, uint32_t a1, uint32_t a2, uint32_t a3,
                                         uint32_t b0, uint32_t b1) {
    asm volatile(
        "mma.sync.aligned.m16n8k8.row.col.f32.tf32.tf32.f32 "
        "{%0,%1,%2,%3}, {%4,%5,%6,%7}, {%8,%9}, {%0,%1,%2,%3};"
        : "+f"(c0), "+f"(c1), "+f"(c2), "+f"(c3)
        : "r"(a0), "r"(a1), "r"(a2), "r"(a3), "r"(b0), "r"(b1));
}

__device__ __forceinline__ void ldsm4(uint32_t& r0, uint32_t& r1, uint32_t& r2, uint32_t& r3,
                                      uint32_t addr) {
    asm volatile("ldmatrix.sync.aligned.m8n8.x4.shared.b16 {%0,%1,%2,%3}, [%4];"
                 : "=r"(r0), "=r"(r1), "=r"(r2), "=r"(r3) : "r"(addr));
}

__device__ __forceinline__ void cp_async16(uint32_t saddr, const void* g) {
    asm volatile("cp.async.cg.shared.global [%0], [%1], 16;\n" :: "r"(saddr), "l"(g));
}
__device__ __forceinline__ void cp_commit() { asm volatile("cp.async.commit_group;\n"); }
template<int N>
__device__ __forceinline__ void cp_wait() { asm volatile("cp.async.wait_group %0;\n" :: "n"(N)); }

// ---------------------------------------------------------------------------
// cp.async pipelined tf32 GEMM. BM x 128 tile, BK=32, warp tile 32x32,
// (BM/32)*4 warps. Single __syncthreads per k-iter, issue-before-compute.
// A [M][K] row-major, B [N][K] (k-contiguous), all values pre-rounded tf32.
// SPLIT=1: hi/lo 3-term. SPLIT=0: single.
// Stages: single S=4; split S=3 (BM=128) / S=2 (BM=64).
// EPI: 0 plain; 1 tf32-rounded; 2 hi->C, lo->C2.
// ---------------------------------------------------------------------------
template<int SPLIT, int EPI, int BM>
__global__ void __launch_bounds__(BM * 4)
gemm_cp(const float* __restrict__ A,  const float* __restrict__ Alo,
        const float* __restrict__ Bt, const float* __restrict__ Btlo,
        float* __restrict__ C, float* __restrict__ C2,
        int K, int lda, int ldb, int ldc,
        long long azA, long long azB, long long azC) {
    constexpr int BK     = 32;
    constexpr int LDSR   = 36;                   // floats per smem row
    constexpr int THREADS= BM * 4;
    constexpr int APB    = BM  * LDSR * 4;       // A plane bytes
    constexpr int BPB    = 128 * LDSR * 4;       // B plane bytes
    constexpr int S      = SPLIT ? (BM == 128 ? 3 : 2) : 4;
    constexpr int STAGEB = (SPLIT ? 2 : 1) * (APB + BPB);
    constexpr int A_IT   = (BM * 8) / THREADS;   // float4 loads per thread (A)
    constexpr int B_IT   = 1024 / THREADS;       // float4 loads per thread (B)

    extern __shared__ float sm[];
    const uint32_t sbase = (uint32_t)__cvta_generic_to_shared(sm);

    const int tid  = threadIdx.x;
    const int warp = tid >> 5;
    const int lane = tid & 31;
    const int wm   = (warp >> 2) * 32;
    const int wn   = (warp & 3) * 32;
    const int grp  = lane >> 2;
    const int tig  = lane & 3;

    const int arow   = lane & 15;
    const int aoff16 = (lane >> 4) * 16;
    const int bsel   = (lane >> 4) & 1;
    const int boff16 = ((lane >> 3) & 1) * 16;
    const int brow   = lane & 7;

    const float* Ab  = A  + (size_t)blockIdx.z * azA + (size_t)blockIdx.y * BM * lda;
    const float* Bb  = Bt + (size_t)blockIdx.z * azB + (size_t)blockIdx.x * 128 * ldb;
    const float* A2b = SPLIT ? Alo  + (size_t)blockIdx.z * azA + (size_t)blockIdx.y * BM * lda : nullptr;
    const float* B2b = SPLIT ? Btlo + (size_t)blockIdx.z * azB + (size_t)blockIdx.x * 128 * ldb : nullptr;

    float acc[2][4][4];
#pragma unroll
    for (int i = 0; i < 2; i++)
#pragma unroll
        for (int j = 0; j < 4; j++)
#pragma unroll
            for (int r = 0; r < 4; r++) acc[i][j][r] = 0.f;

    auto issue = [&](int kt) {
        const int k0 = kt * BK;
        const uint32_t sa = sbase + (uint32_t)((kt % S) * STAGEB);
#pragma unroll
        for (int i = 0; i < A_IT; i++) {
            int c = tid + i * THREADS;
            int m = c >> 3, kc = (c & 7) * 4;
            cp_async16(sa + (uint32_t)(m * LDSR + kc) * 4, Ab + (size_t)m * lda + k0 + kc);
        }
#pragma unroll
        for (int i = 0; i < B_IT; i++) {
            int c = tid + i * THREADS;
            int n = c >> 3, kc = (c & 7) * 4;
            cp_async16(sa + APB + (uint32_t)(n * LDSR + kc) * 4, Bb + (size_t)n * ldb + k0 + kc);
        }
        if (SPLIT) {
#pragma unroll
            for (int i = 0; i < A_IT; i++) {
                int c = tid + i * THREADS;
                int m = c >> 3, kc = (c & 7) * 4;
                cp_async16(sa + APB + BPB + (uint32_t)(m * LDSR + kc) * 4,
                           A2b + (size_t)m * lda + k0 + kc);
            }
#pragma unroll
            for (int i = 0; i < B_IT; i++) {
                int c = tid + i * THREADS;
                int n = c >> 3, kc = (c & 7) * 4;
                cp_async16(sa + 2 * APB + BPB + (uint32_t)(n * LDSR + kc) * 4,
                           B2b + (size_t)n * ldb + k0 + kc);
            }
        }
        cp_commit();
    };

    auto compute = [&](int kt) {
        const uint32_t stb   = sbase + (uint32_t)((kt % S) * STAGEB);
        const uint32_t a_hi0 = stb + (uint32_t)(wm + arow) * (LDSR * 4) + aoff16;
        const uint32_t b_hi0 = stb + APB + (uint32_t)(wn + bsel * 8 + brow) * (LDSR * 4) + boff16;
#pragma unroll
        for (int ks = 0; ks < BK / 8; ks++) {
            const uint32_t kb = ks * 32;
            uint32_t ah[2][4], bh[2][4];
#pragma unroll
            for (int mi = 0; mi < 2; mi++)
                ldsm4(ah[mi][0], ah[mi][1], ah[mi][2], ah[mi][3],
                      a_hi0 + mi * (16 * LDSR * 4) + kb);
#pragma unroll
            for (int p = 0; p < 2; p++)
                ldsm4(bh[p][0], bh[p][1], bh[p][2], bh[p][3],
                      b_hi0 + p * (16 * LDSR * 4) + kb);

            uint32_t al[2][4], bl[2][4];
            if (SPLIT) {
#pragma unroll
                for (int mi = 0; mi < 2; mi++)
                    ldsm4(al[mi][0], al[mi][1], al[mi][2], al[mi][3],
                          a_hi0 + (APB + BPB) + mi * (16 * LDSR * 4) + kb);
#pragma unroll
                for (int p = 0; p < 2; p++)
                    ldsm4(bl[p][0], bl[p][1], bl[p][2], bl[p][3],
                          b_hi0 + (APB + BPB) + p * (16 * LDSR * 4) + kb);
            }
#pragma unroll
            for (int mi = 0; mi < 2; mi++)
#pragma unroll
                for (int ni = 0; ni < 4; ni++) {
                    const int p = ni >> 1, q = (ni & 1) * 2;
                    mma_tf32(acc[mi][ni][0], acc[mi][ni][1], acc[mi][ni][2], acc[mi][ni][3],
                             ah[mi][0], ah[mi][1], ah[mi][2], ah[mi][3],
                             bh[p][q], bh[p][q + 1]);
                    if (SPLIT) {
                        mma_tf32(acc[mi][ni][0], acc[mi][ni][1], acc[mi][ni][2], acc[mi][ni][3],
                                 al[mi][0], al[mi][1], al[mi][2], al[mi][3],
                                 bh[p][q], bh[p][q + 1]);
                        mma_tf32(acc[mi][ni][0], acc[mi][ni][1], acc[mi][ni][2], acc[mi][ni][3],
                                 ah[mi][0], ah[mi][1], ah[mi][2], ah[mi][3],
                                 bl[p][q], bl[p][q + 1]);
                    }
                }
        }
    };

    const int KT = K / BK;
    // Prologue: issue stages 0..S-2
#pragma unroll
    for (int i = 0; i < S - 1; i++) issue(i);

    for (int kt = 0; kt < KT; kt++) {
        cp_wait<S - 2>();
        __syncthreads();
        if (kt + S - 1 < KT) issue(kt + S - 1); else cp_commit();
        compute(kt);
    }

    C += (size_t)blockIdx.z * azC;
    if (EPI == 2) C2 += (size_t)blockIdx.z * azC;
#pragma unroll
    for (int mi = 0; mi < 2; mi++) {
        int m0 = blockIdx.y * BM + wm + mi * 16 + grp;
#pragma unroll
        for (int ni = 0; ni < 4; ni++) {
            int n = blockIdx.x * 128 + wn + ni * 8 + tig * 2;
#pragma unroll
            for (int half = 0; half < 2; half++) {
                size_t off = (size_t)(m0 + half * 8) * ldc + n;
                float v0 = acc[mi][ni][half * 2], v1 = acc[mi][ni][half * 2 + 1];
                if (EPI == 0) {
                    *(float2*)(C + off) = make_float2(v0, v1);
                } else if (EPI == 1) {
                    *(float2*)(C + off) = make_float2(tf32r(v0), tf32r(v1));
                } else {
                    float h0 = tf32r(v0), h1 = tf32r(v1);
                    *(float2*)(C  + off) = make_float2(h0, h1);
                    *(float2*)(C2 + off) = make_float2(tf32r(v0 - h0), tf32r(v1 - h1));
                }
            }
        }
    }
}

// ---------------------------------------------------------------------------
__global__ void split_kernel(const float* __restrict__ in, float* __restrict__ hi,
                             float* __restrict__ lo, int n) {
    int i = blockIdx.x * blockDim.x + threadIdx.x;
    if (i >= n) return;
    float v = in[i];
    float h = tf32r(v);
    hi[i] = h;
    lo[i] = tf32r(v - h);
}

// ---------------------------------------------------------------------------
template<int SPLIT>
__global__ void transpose_round(const float* __restrict__ in,
                                float* __restrict__ outHi, float* __restrict__ outLo,
                                int K, int N, long long inBatch, long long outBatch) {
    __shared__ float tile[32][33];
    const float* inb = in + (size_t)blockIdx.z * inBatch;
    float* oh = outHi + (size_t)blockIdx.z * outBatch;
    float* ol = SPLIT ? outLo + (size_t)blockIdx.z * outBatch : nullptr;
    int n0 = blockIdx.x * 32, k0 = blockIdx.y * 32;
#pragma unroll
    for (int i = threadIdx.y; i < 32; i += 8)
        tile[i][threadIdx.x] = inb[(size_t)(k0 + i) * N + n0 + threadIdx.x];
    __syncthreads();
#pragma unroll
    for (int i = threadIdx.y; i < 32; i += 8) {
        float v = tile[threadIdx.x][i];
        size_t off = (size_t)(n0 + i) * K + k0 + threadIdx.x;
        float h = tf32r(v);
        oh[off] = h;
        if (SPLIT) ol[off] = tf32r(v - h);
    }
}

// ---------------------------------------------------------------------------
__global__ void rope_norm_kernel(float* __restrict__ x, const float* __restrict__ w,
                                 int nrows, int heads, int stride) {
    int gid  = blockIdx.x * blockDim.x + threadIdx.x;
    int wid  = gid >> 5;
    int lane = threadIdx.x & 31;
    if (wid >= nrows) return;
    int pos = (wid / heads) % C_T;

    float* row = x + (size_t)wid * stride;
    float a  = row[lane];
    float b2 = row[lane + 32];
    float c  = row[lane + 64];
    float e  = row[lane + 96];

    double invd = exp(-log(10000.0) * (double)(2 * lane) / 64.0);
    double ang  = (double)pos * invd;
    float cs = (float)cos(ang);
    float sn = (float)sin(ang);

    float r1 = a * cs - b2 * sn;
    float r2 = a * sn + b2 * cs;

    float ss = r1 * r1 + r2 * r2 + c * c + e * e;
#pragma unroll
    for (int off = 16; off; off >>= 1) ss += __shfl_xor_sync(0xffffffffu, ss, off);
    float rms = rsqrtf(ss * (1.0f / 128.0f) + 1e-6f);

    row[lane]      = r1 * rms * w[lane];
    row[lane + 32] = r2 * rms * w[lane + 32];
    row[lane + 64] = c  * rms * w[lane + 64];
    row[lane + 96] = e  * rms * w[lane + 96];
}

// ---------------------------------------------------------------------------
// Attention: block per (t, b); 16 warps = 16 heads. K/V staged through smem
// in chunks of 32 keys shared by all heads.
// ---------------------------------------------------------------------------
__global__ void __launch_bounds__(512)
attn_kernel(const float* __restrict__ q, const float* __restrict__ kv,
            const float* __restrict__ sink, float* __restrict__ att) {
    __shared__ float skv[32 * 2 * C_D];

    int t = blockIdx.x, b = blockIdx.y;
    int h    = threadIdx.x >> 5;
    int lane = threadIdx.x & 31;
    int tid  = threadIdx.x;
    int token = b * C_T + t;

    const float4* q4p = (const float4*)(q + (size_t)token * (C_H * C_D) + h * C_D);
    float4 qv = q4p[lane];

    const float scale = 0.08838834764831845f;
    float m = -1e30f, ssum = 0.f;
    float4 av = make_float4(0.f, 0.f, 0.f, 0.f);

    int s0 = t - (C_WIN - 1);
    if (s0 < 0) s0 = 0;

    for (int c0 = s0; c0 <= t; c0 += 32) {
        int cnt = t - c0 + 1;
        if (cnt > 32) cnt = 32;
        __syncthreads();
        const float4* src = (const float4*)(kv + (size_t)(b * C_T + c0) * (2 * C_D));
        for (int i = tid; i < cnt * 64; i += 512)
            ((float4*)skv)[i] = src[i];
        __syncthreads();

        for (int j = 0; j < cnt; j++) {
            const float4* krow = (const float4*)(skv + j * (2 * C_D));
            float4 kvec = krow[lane];
            float d = qv.x * kvec.x + qv.y * kvec.y + qv.z * kvec.z + qv.w * kvec.w;
#pragma unroll
            for (int off = 16; off; off >>= 1) d += __shfl_xor_sync(0xffffffffu, d, off);
            d *= scale;

            float mn   = fmaxf(m, d);
            float corr = __expf(m - mn);
            float p    = __expf(d - mn);

            float4 vvec = krow[32 + lane];
            ssum = ssum * corr + p;
            av.x = av.x * corr + p * vvec.x;
            av.y = av.y * corr + p * vvec.y;
            av.z = av.z * corr + p * vvec.z;
            av.w = av.w * corr + p * vvec.w;
            m = mn;
        }
    }

    float sl   = sink[h];
    float mn   = fmaxf(m, sl);
    float corr = __expf(m - mn);
    ssum = ssum * corr + __expf(sl - mn);
    float inv = corr / ssum;

    float4* orow = (float4*)(att + (size_t)token * (C_H * C_D) + h * C_D);
    orow[lane] = make_float4(tf32r(av.x * inv), tf32r(av.y * inv),
                             tf32r(av.z * inv), tf32r(av.w * inv));
}

// ---------------------------------------------------------------------------
extern "C" void kernel_launch(void* const* d_in, const int* in_sizes, int n_in,
                              void* d_out, int out_size) {
    const float* h_in     = (const float*)d_in[0];
    const float* wq_comp  = (const float*)d_in[1];
    const float* wq_up    = (const float*)d_in[2];
    const float* wk       = (const float*)d_in[3];
    const float* wv       = (const float*)d_in[4];
    const float* q_norm_w = (const float*)d_in[5];
    const float* k_norm_w = (const float*)d_in[6];
    const float* sink     = (const float*)d_in[7];
    const float* out_w1   = (const float*)d_in[8];
    const float* out_w2   = (const float*)d_in[9];
    float* out = (float*)d_out;

    float *h_hi, *h_lo, *hc_hi, *hc_lo, *q, *kv, *att, *y1;
    float *wqcT_hi, *wqcT_lo, *wquT_hi, *wquT_lo, *wkvT_hi, *wkvT_lo, *w1T, *w2T;
    cudaGetSymbolAddress((void**)&h_hi,  g_h_hi);
    cudaGetSymbolAddress((void**)&h_lo,  g_h_lo);
    cudaGetSymbolAddress((void**)&hc_hi, g_hc_hi);
    cudaGetSymbolAddress((void**)&hc_lo, g_hc_lo);
    cudaGetSymbolAddress((void**)&q,     g_q);
    cudaGetSymbolAddress((void**)&kv,    g_kv);
    cudaGetSymbolAddress((void**)&att,   g_att);
    cudaGetSymbolAddress((void**)&y1,    g_y1);
    cudaGetSymbolAddress((void**)&wqcT_hi, g_wqcT_hi);
    cudaGetSymbolAddress((void**)&wqcT_lo, g_wqcT_lo);
    cudaGetSymbolAddress((void**)&wquT_hi, g_wquT_hi);
    cudaGetSymbolAddress((void**)&wquT_lo, g_wquT_lo);
    cudaGetSymbolAddress((void**)&wkvT_hi, g_wkvT_hi);
    cudaGetSymbolAddress((void**)&wkvT_lo, g_wkvT_lo);
    cudaGetSymbolAddress((void**)&w1T,   g_w1T);
    cudaGetSymbolAddress((void**)&w2T,   g_w2T);

    // smem sizes
    constexpr int APB128 = 128 * 36 * 4, APB64 = 64 * 36 * 4, BPB = 128 * 36 * 4;
    constexpr int SM_SINGLE_128 = 4 * (APB128 + BPB);          // 147456
    constexpr int SM_SPLIT_128  = 3 * 2 * (APB128 + BPB);      // 221184
    constexpr int SM_SPLIT_64   = 2 * 2 * (APB64 + BPB);       // 110592
    cudaFuncSetAttribute(gemm_cp<1,2,64>,  cudaFuncAttributeMaxDynamicSharedMemorySize, SM_SPLIT_64);
    cudaFuncSetAttribute(gemm_cp<1,0,64>,  cudaFuncAttributeMaxDynamicSharedMemorySize, SM_SPLIT_64);
    cudaFuncSetAttribute(gemm_cp<1,0,128>, cudaFuncAttributeMaxDynamicSharedMemorySize, SM_SPLIT_128);
    cudaFuncSetAttribute(gemm_cp<0,1,128>, cudaFuncAttributeMaxDynamicSharedMemorySize, SM_SINGLE_128);
    cudaFuncSetAttribute(gemm_cp<0,0,128>, cudaFuncAttributeMaxDynamicSharedMemorySize, SM_SINGLE_128);

    dim3 tb(32, 8);

    // --- packing / pre-rounding ---
    split_kernel<<<(C_TOK * C_HID + 255) / 256, 256>>>(h_in, h_hi, h_lo, C_TOK * C_HID);
    transpose_round<1><<<dim3(C_QC/32, C_HID/32, 1), tb>>>(wq_comp, wqcT_hi, wqcT_lo, C_HID, C_QC, 0, 0);
    transpose_round<1><<<dim3(C_H*C_D/32, C_QC/32, 1), tb>>>(wq_up, wquT_hi, wquT_lo, C_QC, C_H*C_D, 0, 0);
    transpose_round<1><<<dim3(C_D/32, C_HID/32, 1), tb>>>(wk, wkvT_hi, wkvT_lo, C_HID, C_D, 0, 0);
    transpose_round<1><<<dim3(C_D/32, C_HID/32, 1), tb>>>(wv, wkvT_hi + (size_t)C_D*C_HID,
                                                          wkvT_lo + (size_t)C_D*C_HID, C_HID, C_D, 0, 0);
    transpose_round<0><<<dim3(C_INTER/32, (C_H/C_G)*C_D/32, C_G), tb>>>(
        out_w1, w1T, nullptr, (C_H/C_G)*C_D, C_INTER,
        (long long)(C_H/C_G)*C_D*C_INTER, (long long)C_INTER*(C_H/C_G)*C_D);
    transpose_round<0><<<dim3(C_HID/32, C_G*C_INTER/32, 1), tb>>>(
        out_w2, w2T, nullptr, C_G*C_INTER, C_HID, 0, 0);

    // --- 1) hc = h @ wq_comp (split, BM=64, hi/lo out) ---
    gemm_cp<1,2,64><<<dim3(C_QC/128, C_TOK/64, 1), 256, SM_SPLIT_64>>>(
        h_hi, h_lo, wqcT_hi, wqcT_lo, hc_hi, hc_lo,
        C_HID, C_HID, C_HID, C_QC, 0, 0, 0);

    // --- 2) q = hc @ wq_up (split, BM=128) ---
    gemm_cp<1,0,128><<<dim3(C_H*C_D/128, C_TOK/128, 1), 512, SM_SPLIT_128>>>(
        hc_hi, hc_lo, wquT_hi, wquT_lo, q, nullptr,
        C_QC, C_QC, C_QC, C_H*C_D, 0, 0, 0);

    // --- 3) kv = h @ wkv (split, BM=64) ---
    gemm_cp<1,0,64><<<dim3(2*C_D/128, C_TOK/64, 1), 256, SM_SPLIT_64>>>(
        h_hi, h_lo, wkvT_hi, wkvT_lo, kv, nullptr,
        C_HID, C_HID, C_HID, 2*C_D, 0, 0, 0);

    // --- 4) RoPE + RMSNorm ---
    {
        int rows = C_TOK * C_H;
        rope_norm_kernel<<<(rows * 32 + 255) / 256, 256>>>(q, q_norm_w, rows, C_H, C_D);
    }
    {
        int rows = C_TOK;
        rope_norm_kernel<<<(rows * 32 + 255) / 256, 256>>>(kv, k_norm_w, rows, 1, 2*C_D);
    }

    // --- 5) attention (tf32-rounded output) ---
    attn_kernel<<<dim3(C_T, C_B), 512>>>(q, kv, sink, att);

    // --- 6) y1 = grouped att @ w1 (single, z-batched, rounded out) ---
    gemm_cp<0,1,128><<<dim3(C_INTER/128, C_TOK/128, C_G), 512, SM_SINGLE_128>>>(
        att, nullptr, w1T, nullptr, y1, nullptr,
        (C_H/C_G)*C_D, C_H*C_D, (C_H/C_G)*C_D, C_G*C_INTER,
        (long long)(C_H/C_G)*C_D,
        (long long)C_INTER*(C_H/C_G)*C_D,
        (long long)C_INTER);

    // --- 7) out = y1 @ out_w2 (single, BM=128) ---
    gemm_cp<0,0,128><<<dim3(C_HID/128, C_TOK/128, 1), 512, SM_SINGLE_128>>>(
        y1, nullptr, w2T, nullptr, out, nullptr,
        C_G*C_INTER, C_G*C_INTER, C_G*C_INTER, C_HID, 0, 0, 0);
}